// round 4
// baseline (speedup 1.0000x reference)
#include <cuda_runtime.h>
#include <math.h>

#define N_ 20000
#define E_ 320000
#define G_ 128
#define H_ 64
#define L_ 4
#define AVG_D_LOG 2.8332133440562162f  /* log(17.0) */

typedef unsigned long long ull;

/* ------------------------------------------------------------------ */
/* Scratch                                                             */
/* ------------------------------------------------------------------ */
__device__ int   g_degi[N_];
__device__ float g_amp[N_], g_att[N_];
__device__ int   g_rowoff[N_ + 1];
__device__ int   g_cursor[N_];
__device__ int   g_psrc[E_], g_pdst[E_];
__device__ float g_x[N_ * H_];
__device__ float g_m[E_ * H_];
__device__ float g_agg[N_ * 4 * H_];
__device__ float g_gsum[G_ * H_];
__device__ float g_gcnt[G_];

/* ------------------------------------------------------------------ */
/* Packed f32x2 helpers                                                */
/* ------------------------------------------------------------------ */
__device__ __forceinline__ ull pk2(float x, float y)
{
    ull r;
    asm("mov.b64 %0, {%1,%2};" : "=l"(r) : "f"(x), "f"(y));
    return r;
}
__device__ __forceinline__ void fma2(ull& d, ull a, ull b)
{
    asm("fma.rn.f32x2 %0, %1, %2, %0;" : "+l"(d) : "l"(a), "l"(b));
}
__device__ __forceinline__ void upk2(ull v, float& x, float& y)
{
    asm("mov.b64 {%0,%1}, %2;" : "=f"(x), "=f"(y) : "l"(v));
}

/* ------------------------------------------------------------------ */
/* Setup                                                               */
/* ------------------------------------------------------------------ */
__global__ void k_zero()
{
    int i = blockIdx.x * blockDim.x + threadIdx.x;
    if (i < N_)       g_degi[i] = 0;
    if (i < G_)       g_gcnt[i] = 0.f;
    if (i < G_ * H_)  g_gsum[i] = 0.f;
}

__global__ void k_count(const int* __restrict__ dst)
{
    int e = blockIdx.x * blockDim.x + threadIdx.x;
    if (e < E_) atomicAdd(&g_degi[dst[e]], 1);
}

__global__ void k_gcnt(const int* __restrict__ gid)
{
    int n = blockIdx.x * blockDim.x + threadIdx.x;
    if (n < N_) atomicAdd(&g_gcnt[gid[n]], 1.0f);
}

/* 1024 threads, 20 elems/thread, shuffle-based block scan (R2 version)*/
__global__ void k_scan()
{
    int t  = threadIdx.x;
    int i0 = t * 20;
    int loc[20];
    int s = 0;
#pragma unroll
    for (int k = 0; k < 20; k++) {
        int i = i0 + k;
        int v = (i < N_) ? g_degi[i] : 0;
        loc[k] = s;
        s += v;
    }
    int lane = t & 31, w = t >> 5;
    int x = s;
#pragma unroll
    for (int off = 1; off < 32; off <<= 1) {
        int y = __shfl_up_sync(0xffffffffu, x, off);
        if (lane >= off) x += y;
    }
    __shared__ int wsum[32];
    if (lane == 31) wsum[w] = x;
    __syncthreads();
    if (w == 0) {
        int y = wsum[lane];
#pragma unroll
        for (int off = 1; off < 32; off <<= 1) {
            int z = __shfl_up_sync(0xffffffffu, y, off);
            if (lane >= off) y += z;
        }
        wsum[lane] = y;
    }
    __syncthreads();
    int base = x - s + ((w > 0) ? wsum[w - 1] : 0);
#pragma unroll
    for (int k = 0; k < 20; k++) {
        int i = i0 + k;
        if (i <= N_) g_rowoff[i] = base + loc[k];
    }
}

__global__ void k_scalers()
{
    int i = blockIdx.x * blockDim.x + threadIdx.x;
    if (i >= N_) return;
    float d    = (float)g_degi[i];
    float logd = logf(d + 1.0f);
    g_amp[i] = logd / AVG_D_LOG;
    g_att[i] = AVG_D_LOG / fmaxf(logd, 1e-5f);
    g_cursor[i] = g_rowoff[i];
}

__global__ void k_scatter(const int* __restrict__ src, const int* __restrict__ dst)
{
    int e = blockIdx.x * blockDim.x + threadIdx.x;
    if (e >= E_) return;
    int d = dst[e];
    int p = atomicAdd(&g_cursor[d], 1);
    g_psrc[p] = src[e];
    g_pdst[p] = d;
}

/* ------------------------------------------------------------------ */
/* Embedding                                                           */
/* ------------------------------------------------------------------ */
__global__ void k_embed(const float* __restrict__ h,
                        const float* __restrict__ embW,
                        const float* __restrict__ embB)
{
    int id = blockIdx.x * blockDim.x + threadIdx.x;
    if (id >= N_ * H_) return;
    int n = id >> 6, c = id & 63;
    const float* hr = h + n * 16;
    float a = embB[c];
#pragma unroll
    for (int k = 0; k < 16; k++)
        a = fmaf(hr[k], embW[k * H_ + c], a);
    g_x[id] = a;
}

/* ------------------------------------------------------------------ */
/* Edge pretrans GEMM: BM=64 edges, BN=64, K=128 as 4 subtiles of 32.  */
/* 256 threads, 4 rows x 4 cols per thread, N-pair FFMA2 accumulators. */
/* A stored duplicated (a,a) as ull; B natural floats read as pairs.   */
/* Inner loop: 4 LDS.64(A,bcast) + 2 LDS.64(B) + 8 FFMA2 = FMA-bound.  */
/* ------------------------------------------------------------------ */
__global__ void __launch_bounds__(256)
k_edge(const float* __restrict__ preW, const float* __restrict__ preB)
{
    __shared__ ull   sAd[64][33];     /* dup'd A subtile [edge][k]          */
    __shared__ float sB[32][68];      /* B subtile, natural [k][col]        */
    __shared__ int   sIdx[2][64];

    int t  = threadIdx.x;
    int e0 = blockIdx.x * 64;
    int tx = t & 15, ty = t >> 4;

    if (t < 64) {
        sIdx[0][t] = g_psrc[e0 + t];
        sIdx[1][t] = g_pdst[e0 + t];
    }

    /* init accumulators with bias pairs: cols (2tx,2tx+1), (32+2tx,+1) */
    ull b0 = *(const ull*)(preB + 2 * tx);
    ull b1 = *(const ull*)(preB + 32 + 2 * tx);
    ull acc[4][2];
#pragma unroll
    for (int i = 0; i < 4; i++) { acc[i][0] = b0; acc[i][1] = b1; }
    __syncthreads();

#pragma unroll
    for (int half = 0; half < 2; half++) {
#pragma unroll
        for (int ks = 0; ks < 2; ks++) {
            /* B subtile: 32 rows x 64 cols, natural layout */
#pragma unroll
            for (int r = 0; r < 2; r++) {
                int li = t + 256 * r;
                int kl = li >> 4, c4 = li & 15;
                float4 wv = *(const float4*)(preW + (half * 64 + ks * 32 + kl) * 64 + c4 * 4);
                *(float4*)&sB[kl][c4 * 4] = wv;
            }
            /* A subtile gather: 64 edges x 32 k, store duplicated */
#pragma unroll
            for (int r = 0; r < 2; r++) {
                int li = t + 256 * r;
                int e = li >> 3, c4 = li & 7;
                int nd = sIdx[half][e];
                float4 v = *(const float4*)(g_x + nd * 64 + ks * 32 + c4 * 4);
                sAd[e][c4 * 4 + 0] = pk2(v.x, v.x);
                sAd[e][c4 * 4 + 1] = pk2(v.y, v.y);
                sAd[e][c4 * 4 + 2] = pk2(v.z, v.z);
                sAd[e][c4 * 4 + 3] = pk2(v.w, v.w);
            }
            __syncthreads();
#pragma unroll 4
            for (int kk = 0; kk < 32; kk++) {
                ull B0 = *(const ull*)&sB[kk][2 * tx];
                ull B1 = *(const ull*)&sB[kk][32 + 2 * tx];
                ull A0 = sAd[ty * 4 + 0][kk];
                ull A1 = sAd[ty * 4 + 1][kk];
                ull A2 = sAd[ty * 4 + 2][kk];
                ull A3 = sAd[ty * 4 + 3][kk];
                fma2(acc[0][0], A0, B0); fma2(acc[0][1], A0, B1);
                fma2(acc[1][0], A1, B0); fma2(acc[1][1], A1, B1);
                fma2(acc[2][0], A2, B0); fma2(acc[2][1], A2, B1);
                fma2(acc[3][0], A3, B0); fma2(acc[3][1], A3, B1);
            }
            __syncthreads();
        }
    }

    /* epilogue: rows e0+ty*4+i, packed col pairs -> STG.64, coalesced */
#pragma unroll
    for (int i = 0; i < 4; i++) {
        float* o = g_m + (size_t)(e0 + ty * 4 + i) * 64;
        *(ull*)(o + 2 * tx)      = acc[i][0];
        *(ull*)(o + 32 + 2 * tx) = acc[i][1];
    }
}

/* ------------------------------------------------------------------ */
/* Aggregate: warp per node, CSR walk -> mean/max/min/std              */
/* ------------------------------------------------------------------ */
__global__ void k_agg()
{
    int gw   = (blockIdx.x * blockDim.x + threadIdx.x) >> 5;
    int lane = threadIdx.x & 31;
    if (gw >= N_) return;

    int r0 = g_rowoff[gw], r1 = g_rowoff[gw + 1];
    float sx = 0.f, sy = 0.f, qx = 0.f, qy = 0.f;
    float mxx = -INFINITY, mxy = -INFINITY;
    float mnx =  INFINITY, mny =  INFINITY;

    const float2* M = (const float2*)g_m;
    for (int p = r0; p < r1; p++) {
        float2 v = M[p * 32 + lane];
        sx += v.x; sy += v.y;
        qx = fmaf(v.x, v.x, qx); qy = fmaf(v.y, v.y, qy);
        mxx = fmaxf(mxx, v.x); mxy = fmaxf(mxy, v.y);
        mnx = fminf(mnx, v.x); mny = fminf(mny, v.y);
    }
    int   deg  = r1 - r0;
    float degc = fmaxf((float)deg, 1.0f);
    float meanx = sx / degc, meany = sy / degc;
    float msqx  = qx / degc, msqy  = qy / degc;
    float stdx = sqrtf(fmaxf(msqx - meanx * meanx, 0.f) + 1e-5f);
    float stdy = sqrtf(fmaxf(msqy - meany * meany, 0.f) + 1e-5f);
    if (deg == 0) { mxx = mxy = 0.f; mnx = mny = 0.f; }

    float2* A = (float2*)(g_agg + gw * (4 * H_));
    A[lane]      = make_float2(meanx, meany);
    A[32 + lane] = make_float2(mxx, mxy);
    A[64 + lane] = make_float2(mnx, mny);
    A[96 + lane] = make_float2(stdx, stdy);
}

/* ------------------------------------------------------------------ */
/* Fused posttrans + mixing (R3 version, theoretically FMA-bound)      */
/* ------------------------------------------------------------------ */
__global__ void __launch_bounds__(256, 2)
k_postmix(const float* __restrict__ postW, const float* __restrict__ postB,
          const float* __restrict__ mixW,  const float* __restrict__ mixB,
          const float* __restrict__ snorm)
{
    __shared__ float sY[64][66];                 /* y transposed: [k][node]    */
    __shared__ float sAmp[64], sAtt[64];
    __shared__ __align__(16) unsigned char uBuf[32 * 66 * 4 + 32 * 65 * 8];
    float (*sA)[66]  = (float(*)[66])uBuf;
    ull   (*sBd)[65] = (ull(*)[65])(uBuf + 32 * 66 * 4);
    float (*sW)[68]  = (float(*)[68])uBuf;       /* stage2 reuse */

    int t  = threadIdx.x;
    int n0 = blockIdx.x * 64;
    int tx = t & 15, ty = t >> 4;

    if (t < 64) {
        int n = n0 + t;
        sAmp[t] = (n < N_) ? g_amp[n] : 0.f;
        sAtt[t] = (n < N_) ? g_att[n] : 0.f;
    }
    __syncthreads();

    /* ---------------- stage 1: posttrans ---------------- */
    ull acc[2][4];
#pragma unroll
    for (int j = 0; j < 4; j++) {
        float b = postB[j * 16 + tx];
        ull bb = pk2(b, b);
        acc[0][j] = bb; acc[1][j] = bb;
    }

    for (int kt = 0; kt < 26; kt++) {
#pragma unroll
        for (int r = 0; r < 2; r++) {
            int li = t + 256 * r;
            int kl = li >> 4, c4 = li & 15;
            float4 wv = *(const float4*)(postW + (kt * 32 + kl) * 64 + c4 * 4);
            sBd[kl][c4 * 4 + 0] = pk2(wv.x, wv.x);
            sBd[kl][c4 * 4 + 1] = pk2(wv.y, wv.y);
            sBd[kl][c4 * 4 + 2] = pk2(wv.z, wv.z);
            sBd[kl][c4 * 4 + 3] = pk2(wv.w, wv.w);
        }
#pragma unroll
        for (int r = 0; r < 8; r++) {
            int li = t + 256 * r;
            int nl = li >> 5, kl = li & 31;
            int n  = n0 + nl;
            float v = 0.f;
            if (n < N_) {
                if (kt < 8)       v = g_agg[n * 256 + kt * 32 + kl];
                else if (kt < 16) v = g_agg[n * 256 + (kt - 8)  * 32 + kl] * sAmp[nl];
                else if (kt < 24) v = g_agg[n * 256 + (kt - 16) * 32 + kl] * sAtt[nl];
                else              v = g_x[n * 64 + (kt - 24) * 32 + kl];
            }
            sA[kl][nl] = v;
        }
        __syncthreads();
#pragma unroll 4
        for (int kk = 0; kk < 32; kk++) {
            ull A0 = *(const ull*)&sA[kk][ty * 4 + 0];
            ull A1 = *(const ull*)&sA[kk][ty * 4 + 2];
#pragma unroll
            for (int j = 0; j < 4; j++) {
                ull B = sBd[kk][j * 16 + tx];
                fma2(acc[0][j], A0, B);
                fma2(acc[1][j], A1, B);
            }
        }
        __syncthreads();
    }

    /* y -> sY transposed [k][node] */
#pragma unroll
    for (int i2 = 0; i2 < 2; i2++) {
        int r = ty * 4 + 2 * i2;
#pragma unroll
        for (int j = 0; j < 4; j++) {
            float lo, hi;
            upk2(acc[i2][j], lo, hi);
            sY[j * 16 + tx][r]     = lo;
            sY[j * 16 + tx][r + 1] = hi;
        }
    }
    __syncthreads();

    /* ---------------- stage 2: mixing ---------------- */
#pragma unroll
    for (int r = 0; r < 4; r++) {
        int li = t + 256 * r;
        int kl = li >> 4, c4 = li & 15;
        *(float4*)&sW[kl][c4 * 4] = *(const float4*)(mixW + kl * 64 + c4 * 4);
    }
    ull macc[2][4];
#pragma unroll
    for (int j = 0; j < 4; j++) {
        float b = mixB[tx * 4 + j];
        ull bb = pk2(b, b);
        macc[0][j] = bb; macc[1][j] = bb;
    }
    __syncthreads();

#pragma unroll 4
    for (int kk = 0; kk < 64; kk++) {
        ull A0 = *(const ull*)&sY[kk][ty * 4 + 0];
        ull A1 = *(const ull*)&sY[kk][ty * 4 + 2];
        float4 b = *(const float4*)&sW[kk][tx * 4];
        ull B0 = pk2(b.x, b.x), B1 = pk2(b.y, b.y);
        ull B2 = pk2(b.z, b.z), B3 = pk2(b.w, b.w);
        fma2(macc[0][0], A0, B0); fma2(macc[0][1], A0, B1);
        fma2(macc[0][2], A0, B2); fma2(macc[0][3], A0, B3);
        fma2(macc[1][0], A1, B0); fma2(macc[1][1], A1, B1);
        fma2(macc[1][2], A1, B2); fma2(macc[1][3], A1, B3);
    }

    /* epilogue: leaky + snorm + residual */
#pragma unroll
    for (int i2 = 0; i2 < 2; i2++) {
        float v0[4], v1[4];
#pragma unroll
        for (int j = 0; j < 4; j++) upk2(macc[i2][j], v0[j], v1[j]);
        int r = ty * 4 + 2 * i2;
#pragma unroll
        for (int hfl = 0; hfl < 2; hfl++) {
            int n = n0 + r + hfl;
            if (n >= N_) continue;
            float sn = snorm[n];
            float* xp = g_x + n * 64 + tx * 4;
            float4 cur = *(float4*)xp;
            float* vv = hfl ? v1 : v0;
            float u0 = vv[0]; u0 = (u0 > 0.f) ? u0 : 0.01f * u0;
            float u1 = vv[1]; u1 = (u1 > 0.f) ? u1 : 0.01f * u1;
            float u2 = vv[2]; u2 = (u2 > 0.f) ? u2 : 0.01f * u2;
            float u3 = vv[3]; u3 = (u3 > 0.f) ? u3 : 0.01f * u3;
            cur.x += u0 * sn; cur.y += u1 * sn;
            cur.z += u2 * sn; cur.w += u3 * sn;
            *(float4*)xp = cur;
        }
    }
}

/* ------------------------------------------------------------------ */
/* Readout                                                             */
/* ------------------------------------------------------------------ */
__global__ void k_gaccum(const int* __restrict__ gid)
{
    int id = blockIdx.x * blockDim.x + threadIdx.x;
    if (id >= N_ * H_) return;
    int n = id >> 6, c = id & 63;
    atomicAdd(&g_gsum[gid[n] * 64 + c], g_x[id]);
}

__global__ void k_final(const float* __restrict__ r1W, const float* __restrict__ r1B,
                        const float* __restrict__ r2W, const float* __restrict__ r2B,
                        const float* __restrict__ r3W, const float* __restrict__ r3B,
                        float* __restrict__ out)
{
    int g = threadIdx.x;
    if (g >= G_) return;
    float cnt = fmaxf(g_gcnt[g], 1.0f);
    float hg[64];
#pragma unroll
    for (int k = 0; k < 64; k++) hg[k] = g_gsum[g * 64 + k] / cnt;

    float t1[32];
#pragma unroll
    for (int j = 0; j < 32; j++) {
        float a = r1B[j];
        for (int k = 0; k < 64; k++) a = fmaf(hg[k], r1W[k * 32 + j], a);
        t1[j] = fmaxf(a, 0.f);
    }
    float t2[16];
#pragma unroll
    for (int j = 0; j < 16; j++) {
        float a = r2B[j];
        for (int k = 0; k < 32; k++) a = fmaf(t1[k], r2W[k * 16 + j], a);
        t2[j] = fmaxf(a, 0.f);
    }
#pragma unroll
    for (int c = 0; c < 10; c++) {
        float a = r3B[c];
        for (int k = 0; k < 16; k++) a = fmaf(t2[k], r3W[k * 10 + c], a);
        out[g * 10 + c] = a;
    }
}

/* ------------------------------------------------------------------ */
/* Host launch                                                         */
/* ------------------------------------------------------------------ */
extern "C" void kernel_launch(void* const* d_in, const int* in_sizes, int n_in,
                              void* d_out, int out_size)
{
    const float* h      = (const float*)d_in[0];
    const float* snorm  = (const float*)d_in[1];
    const float* embW   = (const float*)d_in[2];
    const float* embB   = (const float*)d_in[3];
    const float* preW   = (const float*)d_in[4];
    const float* preB   = (const float*)d_in[5];
    const float* postW  = (const float*)d_in[6];
    const float* postB  = (const float*)d_in[7];
    const float* mixW   = (const float*)d_in[8];
    const float* mixB   = (const float*)d_in[9];
    const float* r1W    = (const float*)d_in[10];
    const float* r1B    = (const float*)d_in[11];
    const float* r2W    = (const float*)d_in[12];
    const float* r2B    = (const float*)d_in[13];
    const float* r3W    = (const float*)d_in[14];
    const float* r3B    = (const float*)d_in[15];
    const int*   src    = (const int*)d_in[16];
    const int*   dst    = (const int*)d_in[17];
    const int*   gid    = (const int*)d_in[18];
    float* out = (float*)d_out;

    k_zero   <<<(N_ + 255) / 256, 256>>>();
    k_count  <<<(E_ + 255) / 256, 256>>>(dst);
    k_gcnt   <<<(N_ + 255) / 256, 256>>>(gid);
    k_scan   <<<1, 1024>>>();
    k_scalers<<<(N_ + 255) / 256, 256>>>();
    k_scatter<<<(E_ + 255) / 256, 256>>>(src, dst);

    k_embed<<<(N_ * H_ + 255) / 256, 256>>>(h, embW, embB);

    for (int i = 0; i < L_; i++) {
        k_edge   <<<E_ / 64, 256>>>(preW + i * 128 * 64, preB + i * 64);
        k_agg    <<<(N_ * 32 + 255) / 256, 256>>>();
        k_postmix<<<(N_ + 63) / 64, 256>>>(postW + i * 832 * 64, postB + i * 64,
                                           mixW + i * 64 * 64, mixB + i * 64, snorm);
    }

    k_gaccum<<<(N_ * H_ + 255) / 256, 256>>>(gid);
    k_final <<<1, 128>>>(r1W, r1B, r2W, r2B, r3W, r3B, out);
}

// round 6
// speedup vs baseline: 1.1660x; 1.1660x over previous
#include <cuda_runtime.h>
#include <math.h>

#define N_ 20000
#define E_ 320000
#define G_ 128
#define H_ 64
#define L_ 4
#define AVG_D_LOG 2.8332133440562162f  /* log(17.0) */

typedef unsigned long long ull;

/* ------------------------------------------------------------------ */
/* Scratch                                                             */
/* ------------------------------------------------------------------ */
__device__ int   g_degi[N_];
__device__ float g_amp[N_], g_att[N_];
__device__ int   g_rowoff[N_ + 1];
__device__ int   g_cursor[N_];
__device__ int   g_psrc[E_], g_pdst[E_];
__device__ float g_x[N_ * H_];
__device__ float g_m[E_ * H_];
__device__ float g_agg[N_ * 4 * H_];
__device__ float g_y[N_ * H_];
__device__ float g_gsum[G_ * H_];
__device__ float g_gcnt[G_];

/* ------------------------------------------------------------------ */
/* Packed f32x2 helpers                                                */
/* ------------------------------------------------------------------ */
__device__ __forceinline__ ull pk2(float x, float y)
{
    ull r;
    asm("mov.b64 %0, {%1,%2};" : "=l"(r) : "f"(x), "f"(y));
    return r;
}
__device__ __forceinline__ void fma2(ull& d, ull a, ull b)
{
    asm("fma.rn.f32x2 %0, %1, %2, %0;" : "+l"(d) : "l"(a), "l"(b));
}
__device__ __forceinline__ void upk2(ull v, float& x, float& y)
{
    asm("mov.b64 {%0,%1}, %2;" : "=f"(x), "=f"(y) : "l"(v));
}

/* ------------------------------------------------------------------ */
/* Setup                                                               */
/* ------------------------------------------------------------------ */
__global__ void k_zero()
{
    int i = blockIdx.x * blockDim.x + threadIdx.x;
    if (i < N_)       g_degi[i] = 0;
    if (i < G_)       g_gcnt[i] = 0.f;
    if (i < G_ * H_)  g_gsum[i] = 0.f;
}

__global__ void k_count(const int* __restrict__ dst)
{
    int e = blockIdx.x * blockDim.x + threadIdx.x;
    if (e < E_) atomicAdd(&g_degi[dst[e]], 1);
}

__global__ void k_gcnt(const int* __restrict__ gid)
{
    int n = blockIdx.x * blockDim.x + threadIdx.x;
    if (n < N_) atomicAdd(&g_gcnt[gid[n]], 1.0f);
}

/* 1024 threads, 20 elems/thread, shuffle-based block scan             */
__global__ void k_scan()
{
    int t  = threadIdx.x;
    int i0 = t * 20;
    int loc[20];
    int s = 0;
#pragma unroll
    for (int k = 0; k < 20; k++) {
        int i = i0 + k;
        int v = (i < N_) ? g_degi[i] : 0;
        loc[k] = s;
        s += v;
    }
    int lane = t & 31, w = t >> 5;
    int x = s;
#pragma unroll
    for (int off = 1; off < 32; off <<= 1) {
        int y = __shfl_up_sync(0xffffffffu, x, off);
        if (lane >= off) x += y;
    }
    __shared__ int wsum[32];
    if (lane == 31) wsum[w] = x;
    __syncthreads();
    if (w == 0) {
        int y = wsum[lane];
#pragma unroll
        for (int off = 1; off < 32; off <<= 1) {
            int z = __shfl_up_sync(0xffffffffu, y, off);
            if (lane >= off) y += z;
        }
        wsum[lane] = y;
    }
    __syncthreads();
    int base = x - s + ((w > 0) ? wsum[w - 1] : 0);
#pragma unroll
    for (int k = 0; k < 20; k++) {
        int i = i0 + k;
        if (i <= N_) g_rowoff[i] = base + loc[k];
    }
}

__global__ void k_scalers()
{
    int i = blockIdx.x * blockDim.x + threadIdx.x;
    if (i >= N_) return;
    float d    = (float)g_degi[i];
    float logd = logf(d + 1.0f);
    g_amp[i] = logd / AVG_D_LOG;
    g_att[i] = AVG_D_LOG / fmaxf(logd, 1e-5f);
    g_cursor[i] = g_rowoff[i];
}

__global__ void k_scatter(const int* __restrict__ src, const int* __restrict__ dst)
{
    int e = blockIdx.x * blockDim.x + threadIdx.x;
    if (e >= E_) return;
    int d = dst[e];
    int p = atomicAdd(&g_cursor[d], 1);
    g_psrc[p] = src[e];
    g_pdst[p] = d;
}

/* ------------------------------------------------------------------ */
/* Embedding                                                           */
/* ------------------------------------------------------------------ */
__global__ void k_embed(const float* __restrict__ h,
                        const float* __restrict__ embW,
                        const float* __restrict__ embB)
{
    int id = blockIdx.x * blockDim.x + threadIdx.x;
    if (id >= N_ * H_) return;
    int n = id >> 6, c = id & 63;
    const float* hr = h + n * 16;
    float a = embB[c];
#pragma unroll
    for (int k = 0; k < 16; k++)
        a = fmaf(hr[k], embW[k * H_ + c], a);
    g_x[id] = a;
}

/* ------------------------------------------------------------------ */
/* Edge pretrans GEMM (R2 structure + register-prefetch pipeline).     */
/* BM=64 edges, BN=64, K=128 as 2 phases (src half, dst half).         */
/* Phase-1 gather (index chase + LDG.128s) issued right after the      */
/* phase-0 sync so its latency hides under phase-0 compute.            */
/* ------------------------------------------------------------------ */
__global__ void __launch_bounds__(256)
k_edge(const float* __restrict__ preW, const float* __restrict__ preB)
{
    __shared__ float sA[64][68];
    __shared__ float sB[64][68];

    int t  = threadIdx.x;
    int e0 = blockIdx.x * 64;
    int tx = t & 15, ty = t >> 4;

    ull acc[4][2];
#pragma unroll
    for (int i = 0; i < 4; i++) { acc[i][0] = pk2(0.f, 0.f); acc[i][1] = pk2(0.f, 0.f); }

    float4 aR[4], bR[4];

    /* prefetch phase 0: A = x[src], B = preW rows 0..63 */
#pragma unroll
    for (int r = 0; r < 4; r++) {
        int row = 16 * r + ty;
        bR[r] = *(const float4*)(preW + row * 64 + tx * 4);
        int nd = g_psrc[e0 + row];
        aR[r] = *(const float4*)(g_x + nd * 64 + tx * 4);
    }
#pragma unroll
    for (int r = 0; r < 4; r++) {
        int row = 16 * r + ty;
        *(float4*)&sA[row][tx * 4] = aR[r];
        *(float4*)&sB[row][tx * 4] = bR[r];
    }
    __syncthreads();

    /* prefetch phase 1 (hidden under phase-0 compute) */
#pragma unroll
    for (int r = 0; r < 4; r++) {
        int row = 16 * r + ty;
        bR[r] = *(const float4*)(preW + (64 + row) * 64 + tx * 4);
        int nd = g_pdst[e0 + row];
        aR[r] = *(const float4*)(g_x + nd * 64 + tx * 4);
    }

    /* compute phase 0 */
#pragma unroll 8
    for (int kk = 0; kk < 64; kk++) {
        float4 b = *(const float4*)&sB[kk][tx * 4];
        ull B01 = pk2(b.x, b.y);
        ull B23 = pk2(b.z, b.w);
#pragma unroll
        for (int i = 0; i < 4; i++) {
            float a = sA[ty * 4 + i][kk];
            ull A = pk2(a, a);
            fma2(acc[i][0], A, B01);
            fma2(acc[i][1], A, B23);
        }
    }
    __syncthreads();

    /* store phase-1 tiles */
#pragma unroll
    for (int r = 0; r < 4; r++) {
        int row = 16 * r + ty;
        *(float4*)&sA[row][tx * 4] = aR[r];
        *(float4*)&sB[row][tx * 4] = bR[r];
    }
    __syncthreads();

    /* compute phase 1 */
#pragma unroll 8
    for (int kk = 0; kk < 64; kk++) {
        float4 b = *(const float4*)&sB[kk][tx * 4];
        ull B01 = pk2(b.x, b.y);
        ull B23 = pk2(b.z, b.w);
#pragma unroll
        for (int i = 0; i < 4; i++) {
            float a = sA[ty * 4 + i][kk];
            ull A = pk2(a, a);
            fma2(acc[i][0], A, B01);
            fma2(acc[i][1], A, B23);
        }
    }

    float4 bias = *(const float4*)&preB[tx * 4];
#pragma unroll
    for (int i = 0; i < 4; i++) {
        int p = e0 + ty * 4 + i;
        float x0, x1, x2, x3;
        upk2(acc[i][0], x0, x1);
        upk2(acc[i][1], x2, x3);
        float4 o = make_float4(x0 + bias.x, x1 + bias.y, x2 + bias.z, x3 + bias.w);
        *(float4*)(g_m + (size_t)p * 64 + tx * 4) = o;
    }
}

/* ------------------------------------------------------------------ */
/* Aggregate: warp per node, CSR walk -> mean/max/min/std              */
/* ------------------------------------------------------------------ */
__global__ void k_agg()
{
    int gw   = (blockIdx.x * blockDim.x + threadIdx.x) >> 5;
    int lane = threadIdx.x & 31;
    if (gw >= N_) return;

    int r0 = g_rowoff[gw], r1 = g_rowoff[gw + 1];
    float sx = 0.f, sy = 0.f, qx = 0.f, qy = 0.f;
    float mxx = -INFINITY, mxy = -INFINITY;
    float mnx =  INFINITY, mny =  INFINITY;

    const float2* M = (const float2*)g_m;
    for (int p = r0; p < r1; p++) {
        float2 v = M[p * 32 + lane];
        sx += v.x; sy += v.y;
        qx = fmaf(v.x, v.x, qx); qy = fmaf(v.y, v.y, qy);
        mxx = fmaxf(mxx, v.x); mxy = fmaxf(mxy, v.y);
        mnx = fminf(mnx, v.x); mny = fminf(mny, v.y);
    }
    int   deg  = r1 - r0;
    float degc = fmaxf((float)deg, 1.0f);
    float meanx = sx / degc, meany = sy / degc;
    float msqx  = qx / degc, msqy  = qy / degc;
    float stdx = sqrtf(fmaxf(msqx - meanx * meanx, 0.f) + 1e-5f);
    float stdy = sqrtf(fmaxf(msqy - meany * meany, 0.f) + 1e-5f);
    if (deg == 0) { mxx = mxy = 0.f; mnx = mny = 0.f; }

    float2* A = (float2*)(g_agg + gw * (4 * H_));
    A[lane]      = make_float2(meanx, meany);
    A[32 + lane] = make_float2(mxx, mxy);
    A[64 + lane] = make_float2(mnx, mny);
    A[96 + lane] = make_float2(stdx, stdy);
}

/* ------------------------------------------------------------------ */
/* Posttrans GEMM: y = A'[N,832] @ postW + postB                       */
/* sA stride 66 (264B, 8-aligned) for LDS.64 of node pairs.            */
/* ------------------------------------------------------------------ */
__global__ void __launch_bounds__(256)
k_postB(const float* __restrict__ postW, const float* __restrict__ postB)
{
    __shared__ float sA[32][66];
    __shared__ ull   sBd[32][65];
    __shared__ float sAmp[64], sAtt[64];

    int t  = threadIdx.x;
    int n0 = blockIdx.x * 64;
    if (t < 64) {
        int n = n0 + t;
        sAmp[t] = (n < N_) ? g_amp[n] : 0.f;
        sAtt[t] = (n < N_) ? g_att[n] : 0.f;
    }
    __syncthreads();

    int tx = t & 15, ty = t >> 4;
    ull acc[2][4];
#pragma unroll
    for (int j = 0; j < 4; j++) {
        float b = postB[j * 16 + tx];
        ull bb = pk2(b, b);
        acc[0][j] = bb; acc[1][j] = bb;
    }

    for (int kt = 0; kt < 26; kt++) {
#pragma unroll
        for (int r = 0; r < 2; r++) {
            int li = t + 256 * r;
            int kl = li >> 4, c4 = li & 15;
            float4 wv = *(const float4*)(postW + (kt * 32 + kl) * 64 + c4 * 4);
            sBd[kl][c4 * 4 + 0] = pk2(wv.x, wv.x);
            sBd[kl][c4 * 4 + 1] = pk2(wv.y, wv.y);
            sBd[kl][c4 * 4 + 2] = pk2(wv.z, wv.z);
            sBd[kl][c4 * 4 + 3] = pk2(wv.w, wv.w);
        }
#pragma unroll
        for (int r = 0; r < 8; r++) {
            int li = t + 256 * r;
            int nl = li >> 5, kl = li & 31;
            int n  = n0 + nl;
            float v = 0.f;
            if (n < N_) {
                if (kt < 8)       v = g_agg[n * 256 + kt * 32 + kl];
                else if (kt < 16) v = g_agg[n * 256 + (kt - 8)  * 32 + kl] * sAmp[nl];
                else if (kt < 24) v = g_agg[n * 256 + (kt - 16) * 32 + kl] * sAtt[nl];
                else              v = g_x[n * 64 + (kt - 24) * 32 + kl];
            }
            sA[kl][nl] = v;
        }
        __syncthreads();
#pragma unroll 4
        for (int kk = 0; kk < 32; kk++) {
            ull A0 = *(const ull*)&sA[kk][ty * 4 + 0];
            ull A1 = *(const ull*)&sA[kk][ty * 4 + 2];
#pragma unroll
            for (int j = 0; j < 4; j++) {
                ull B = sBd[kk][j * 16 + tx];
                fma2(acc[0][j], A0, B);
                fma2(acc[1][j], A1, B);
            }
        }
        __syncthreads();
    }

#pragma unroll
    for (int i2 = 0; i2 < 2; i2++) {
        int r = ty * 4 + 2 * i2;
#pragma unroll
        for (int j = 0; j < 4; j++) {
            float lo, hi;
            upk2(acc[i2][j], lo, hi);
            int c = j * 16 + tx;
            int n = n0 + r;
            if (n < N_)     g_y[n * 64 + c]       = lo;
            if (n + 1 < N_) g_y[(n + 1) * 64 + c] = hi;
        }
    }
}

/* ------------------------------------------------------------------ */
/* Mix + leaky_relu + snorm + residual (R2 version)                    */
/* ------------------------------------------------------------------ */
__global__ void k_mix(const float* __restrict__ mixW,
                      const float* __restrict__ mixB,
                      const float* __restrict__ snorm)
{
    __shared__ float sY[64][65];
    __shared__ float sW[64][68];

    int t  = threadIdx.x;
    int n0 = blockIdx.x * 64;

#pragma unroll
    for (int r = 0; r < 16; r++) {
        int li = t + 256 * r;
        int nl = li >> 6, kl = li & 63;
        int n  = n0 + nl;
        sY[kl][nl] = (n < N_) ? g_y[n * 64 + kl] : 0.f;
        sW[nl][kl] = mixW[nl * 64 + kl];
    }
    __syncthreads();

    int tx = t & 15, ty = t >> 4;
    ull acc[4][2];
#pragma unroll
    for (int i = 0; i < 4; i++) { acc[i][0] = pk2(0.f, 0.f); acc[i][1] = pk2(0.f, 0.f); }

#pragma unroll 8
    for (int kk = 0; kk < 64; kk++) {
        float4 b = *(const float4*)&sW[kk][tx * 4];
        ull B01 = pk2(b.x, b.y);
        ull B23 = pk2(b.z, b.w);
#pragma unroll
        for (int i = 0; i < 4; i++) {
            float a = sY[kk][ty * 4 + i];
            ull A = pk2(a, a);
            fma2(acc[i][0], A, B01);
            fma2(acc[i][1], A, B23);
        }
    }

#pragma unroll
    for (int i = 0; i < 4; i++) {
        int n = n0 + ty * 4 + i;
        if (n >= N_) continue;
        float sn = snorm[n];
        float v[4];
        upk2(acc[i][0], v[0], v[1]);
        upk2(acc[i][1], v[2], v[3]);
#pragma unroll
        for (int j = 0; j < 4; j++) {
            int c = tx * 4 + j;
            float u = v[j] + mixB[c];
            u = (u > 0.f) ? u : 0.01f * u;
            g_x[n * 64 + c] += u * sn;
        }
    }
}

/* ------------------------------------------------------------------ */
/* Readout                                                             */
/* ------------------------------------------------------------------ */
__global__ void k_gaccum(const int* __restrict__ gid)
{
    int id = blockIdx.x * blockDim.x + threadIdx.x;
    if (id >= N_ * H_) return;
    int n = id >> 6, c = id & 63;
    atomicAdd(&g_gsum[gid[n] * 64 + c], g_x[id]);
}

__global__ void k_final(const float* __restrict__ r1W, const float* __restrict__ r1B,
                        const float* __restrict__ r2W, const float* __restrict__ r2B,
                        const float* __restrict__ r3W, const float* __restrict__ r3B,
                        float* __restrict__ out)
{
    int g = threadIdx.x;
    if (g >= G_) return;
    float cnt = fmaxf(g_gcnt[g], 1.0f);
    float hg[64];
#pragma unroll
    for (int k = 0; k < 64; k++) hg[k] = g_gsum[g * 64 + k] / cnt;

    float t1[32];
#pragma unroll
    for (int j = 0; j < 32; j++) {
        float a = r1B[j];
        for (int k = 0; k < 64; k++) a = fmaf(hg[k], r1W[k * 32 + j], a);
        t1[j] = fmaxf(a, 0.f);
    }
    float t2[16];
#pragma unroll
    for (int j = 0; j < 16; j++) {
        float a = r2B[j];
        for (int k = 0; k < 32; k++) a = fmaf(t1[k], r2W[k * 16 + j], a);
        t2[j] = fmaxf(a, 0.f);
    }
#pragma unroll
    for (int c = 0; c < 10; c++) {
        float a = r3B[c];
        for (int k = 0; k < 16; k++) a = fmaf(t2[k], r3W[k * 10 + c], a);
        out[g * 10 + c] = a;
    }
}

/* ------------------------------------------------------------------ */
/* Host launch                                                         */
/* ------------------------------------------------------------------ */
extern "C" void kernel_launch(void* const* d_in, const int* in_sizes, int n_in,
                              void* d_out, int out_size)
{
    const float* h      = (const float*)d_in[0];
    const float* snorm  = (const float*)d_in[1];
    const float* embW   = (const float*)d_in[2];
    const float* embB   = (const float*)d_in[3];
    const float* preW   = (const float*)d_in[4];
    const float* preB   = (const float*)d_in[5];
    const float* postW  = (const float*)d_in[6];
    const float* postB  = (const float*)d_in[7];
    const float* mixW   = (const float*)d_in[8];
    const float* mixB   = (const float*)d_in[9];
    const float* r1W    = (const float*)d_in[10];
    const float* r1B    = (const float*)d_in[11];
    const float* r2W    = (const float*)d_in[12];
    const float* r2B    = (const float*)d_in[13];
    const float* r3W    = (const float*)d_in[14];
    const float* r3B    = (const float*)d_in[15];
    const int*   src    = (const int*)d_in[16];
    const int*   dst    = (const int*)d_in[17];
    const int*   gid    = (const int*)d_in[18];
    float* out = (float*)d_out;

    k_zero   <<<(N_ + 255) / 256, 256>>>();
    k_count  <<<(E_ + 255) / 256, 256>>>(dst);
    k_gcnt   <<<(N_ + 255) / 256, 256>>>(gid);
    k_scan   <<<1, 1024>>>();
    k_scalers<<<(N_ + 255) / 256, 256>>>();
    k_scatter<<<(E_ + 255) / 256, 256>>>(src, dst);

    k_embed<<<(N_ * H_ + 255) / 256, 256>>>(h, embW, embB);

    for (int i = 0; i < L_; i++) {
        k_edge <<<E_ / 64, 256>>>(preW + i * 128 * 64, preB + i * 64);
        k_agg  <<<(N_ * 32 + 255) / 256, 256>>>();
        k_postB<<<(N_ + 63) / 64, 256>>>(postW + i * 832 * 64, postB + i * 64);
        k_mix  <<<(N_ + 63) / 64, 256>>>(mixW + i * 64 * 64, mixB + i * 64, snorm);
    }

    k_gaccum<<<(N_ * H_ + 255) / 256, 256>>>(gid);
    k_final <<<1, 128>>>(r1W, r1B, r2W, r2B, r3W, r3B, out);
}

// round 7
// speedup vs baseline: 1.3322x; 1.1426x over previous
#include <cuda_runtime.h>
#include <math.h>

#define N_ 20000
#define E_ 320000
#define G_ 128
#define H_ 64
#define L_ 4
#define AVG_D_LOG 2.8332133440562162f  /* log(17.0) */

typedef unsigned long long ull;

/* ------------------------------------------------------------------ */
/* Scratch                                                             */
/* ------------------------------------------------------------------ */
__device__ int   g_degi[N_];
__device__ float g_amp[N_], g_att[N_];
__device__ int   g_rowoff[N_ + 1];
__device__ int   g_cursor[N_];
__device__ int   g_psrc[E_], g_pdst[E_];
__device__ float g_x[N_ * H_];
__device__ float g_m[E_ * H_];
__device__ float g_agg[N_ * 4 * H_];
__device__ float g_y[N_ * H_];
__device__ float g_gsum[G_ * H_];
__device__ float g_gcnt[G_];

/* ------------------------------------------------------------------ */
/* Packed f32x2 helpers                                                */
/* ------------------------------------------------------------------ */
__device__ __forceinline__ ull pk2(float x, float y)
{
    ull r;
    asm("mov.b64 %0, {%1,%2};" : "=l"(r) : "f"(x), "f"(y));
    return r;
}
__device__ __forceinline__ void fma2(ull& d, ull a, ull b)
{
    asm("fma.rn.f32x2 %0, %1, %2, %0;" : "+l"(d) : "l"(a), "l"(b));
}
__device__ __forceinline__ void upk2(ull v, float& x, float& y)
{
    asm("mov.b64 {%0,%1}, %2;" : "=f"(x), "=f"(y) : "l"(v));
}

/* ------------------------------------------------------------------ */
/* Setup — restructured so k_edge (layer 0) is the 6th launch          */
/* ------------------------------------------------------------------ */
/* launch 1 */
__global__ void k_zero()
{
    int i = blockIdx.x * blockDim.x + threadIdx.x;
    if (i < N_)       g_degi[i] = 0;
    if (i < G_)       g_gcnt[i] = 0.f;
    if (i < G_ * H_)  g_gsum[i] = 0.f;
}

/* launch 2: degree count + graph-count fused */
__global__ void k_count_gcnt(const int* __restrict__ dst,
                             const int* __restrict__ gid)
{
    int i = blockIdx.x * blockDim.x + threadIdx.x;
    if (i < E_) atomicAdd(&g_degi[dst[i]], 1);
    if (i < N_) atomicAdd(&g_gcnt[gid[i]], 1.0f);
}

/* launch 3: block scan; also writes g_cursor (no MUFU work here)      */
__global__ void k_scan()
{
    int t  = threadIdx.x;
    int i0 = t * 20;
    int loc[20];
    int s = 0;
#pragma unroll
    for (int k = 0; k < 20; k++) {
        int i = i0 + k;
        int v = (i < N_) ? g_degi[i] : 0;
        loc[k] = s;
        s += v;
    }
    int lane = t & 31, w = t >> 5;
    int x = s;
#pragma unroll
    for (int off = 1; off < 32; off <<= 1) {
        int y = __shfl_up_sync(0xffffffffu, x, off);
        if (lane >= off) x += y;
    }
    __shared__ int wsum[32];
    if (lane == 31) wsum[w] = x;
    __syncthreads();
    if (w == 0) {
        int y = wsum[lane];
#pragma unroll
        for (int off = 1; off < 32; off <<= 1) {
            int z = __shfl_up_sync(0xffffffffu, y, off);
            if (lane >= off) y += z;
        }
        wsum[lane] = y;
    }
    __syncthreads();
    int base = x - s + ((w > 0) ? wsum[w - 1] : 0);
#pragma unroll
    for (int k = 0; k < 20; k++) {
        int i = i0 + k;
        if (i <= N_) {
            int off = base + loc[k];
            g_rowoff[i] = off;
            if (i < N_) g_cursor[i] = off;
        }
    }
}

/* launch 4: degree scalers + embedding fused (independent elementwise)*/
__global__ void k_scalers_embed(const float* __restrict__ h,
                                const float* __restrict__ embW,
                                const float* __restrict__ embB)
{
    int id = blockIdx.x * blockDim.x + threadIdx.x;
    if (id < N_) {
        float d    = (float)g_degi[id];
        float logd = logf(d + 1.0f);
        g_amp[id] = logd / AVG_D_LOG;
        g_att[id] = AVG_D_LOG / fmaxf(logd, 1e-5f);
    }
    if (id < N_ * H_) {
        int n = id >> 6, c = id & 63;
        const float* hr = h + n * 16;
        float a = embB[c];
#pragma unroll
        for (int k = 0; k < 16; k++)
            a = fmaf(hr[k], embW[k * H_ + c], a);
        g_x[id] = a;
    }
}

/* launch 5 */
__global__ void k_scatter(const int* __restrict__ src, const int* __restrict__ dst)
{
    int e = blockIdx.x * blockDim.x + threadIdx.x;
    if (e >= E_) return;
    int d = dst[e];
    int p = atomicAdd(&g_cursor[d], 1);
    g_psrc[p] = src[e];
    g_pdst[p] = d;
}

/* ------------------------------------------------------------------ */
/* Edge pretrans GEMM (exact R2 version, 1145us baseline)              */
/* BM=64 edges, BN=64, K=128 as two 64-tiles (src/dst).                */
/* ------------------------------------------------------------------ */
__global__ void k_edge(const float* __restrict__ preW,
                       const float* __restrict__ preB)
{
    __shared__ float sA[64][68];
    __shared__ float sB[64][68];

    int t  = threadIdx.x;
    int e0 = blockIdx.x * 64;
    int tx = t & 15, ty = t >> 4;

    ull acc[4][2];
#pragma unroll
    for (int i = 0; i < 4; i++) { acc[i][0] = pk2(0.f, 0.f); acc[i][1] = pk2(0.f, 0.f); }

    for (int kt = 0; kt < 2; kt++) {
        /* B tile: preW rows kt*64 .. kt*64+63 */
#pragma unroll
        for (int r = 0; r < 4; r++) {
            int li  = t + 256 * r;          /* float4 index 0..1023 */
            int row = li >> 4, c4 = li & 15;
            float4 wv = *(const float4*)(preW + (kt * 64 + row) * 64 + c4 * 4);
            *(float4*)&sB[row][c4 * 4] = wv;
        }
        /* A tile gather: row e = x[src[p]] (kt=0) or x[dst[p]] (kt=1) */
#pragma unroll
        for (int r = 0; r < 4; r++) {
            int li = t + 256 * r;
            int e = li >> 4, c4 = li & 15;
            int p = e0 + e;
            float4 v = make_float4(0.f, 0.f, 0.f, 0.f);
            if (p < E_) {
                int nd = (kt == 0) ? g_psrc[p] : g_pdst[p];
                v = *(const float4*)(g_x + nd * 64 + c4 * 4);
            }
            *(float4*)&sA[e][c4 * 4] = v;
        }
        __syncthreads();
#pragma unroll 8
        for (int kk = 0; kk < 64; kk++) {
            float4 b = *(const float4*)&sB[kk][tx * 4];
            ull B01 = pk2(b.x, b.y);
            ull B23 = pk2(b.z, b.w);
#pragma unroll
            for (int i = 0; i < 4; i++) {
                float a = sA[ty * 4 + i][kk];
                ull A = pk2(a, a);
                fma2(acc[i][0], A, B01);
                fma2(acc[i][1], A, B23);
            }
        }
        __syncthreads();
    }

    float4 bias = *(const float4*)&preB[tx * 4];
#pragma unroll
    for (int i = 0; i < 4; i++) {
        int p = e0 + ty * 4 + i;
        if (p >= E_) continue;
        float x0, x1, x2, x3;
        upk2(acc[i][0], x0, x1);
        upk2(acc[i][1], x2, x3);
        float4 o = make_float4(x0 + bias.x, x1 + bias.y, x2 + bias.z, x3 + bias.w);
        *(float4*)(g_m + (size_t)p * 64 + tx * 4) = o;
    }
}

/* ------------------------------------------------------------------ */
/* Aggregate: warp per node, CSR walk -> mean/max/min/std              */
/* ------------------------------------------------------------------ */
__global__ void k_agg()
{
    int gw   = (blockIdx.x * blockDim.x + threadIdx.x) >> 5;
    int lane = threadIdx.x & 31;
    if (gw >= N_) return;

    int r0 = g_rowoff[gw], r1 = g_rowoff[gw + 1];
    float sx = 0.f, sy = 0.f, qx = 0.f, qy = 0.f;
    float mxx = -INFINITY, mxy = -INFINITY;
    float mnx =  INFINITY, mny =  INFINITY;

    const float2* M = (const float2*)g_m;
    for (int p = r0; p < r1; p++) {
        float2 v = M[p * 32 + lane];
        sx += v.x; sy += v.y;
        qx = fmaf(v.x, v.x, qx); qy = fmaf(v.y, v.y, qy);
        mxx = fmaxf(mxx, v.x); mxy = fmaxf(mxy, v.y);
        mnx = fminf(mnx, v.x); mny = fminf(mny, v.y);
    }
    int   deg  = r1 - r0;
    float degc = fmaxf((float)deg, 1.0f);
    float meanx = sx / degc, meany = sy / degc;
    float msqx  = qx / degc, msqy  = qy / degc;
    float stdx = sqrtf(fmaxf(msqx - meanx * meanx, 0.f) + 1e-5f);
    float stdy = sqrtf(fmaxf(msqy - meany * meany, 0.f) + 1e-5f);
    if (deg == 0) { mxx = mxy = 0.f; mnx = mny = 0.f; }

    float2* A = (float2*)(g_agg + gw * (4 * H_));
    A[lane]      = make_float2(meanx, meany);
    A[32 + lane] = make_float2(mxx, mxy);
    A[64 + lane] = make_float2(mnx, mny);
    A[96 + lane] = make_float2(stdx, stdy);
}

/* ------------------------------------------------------------------ */
/* Posttrans GEMM (exact R2 version)                                   */
/* ------------------------------------------------------------------ */
__global__ void k_post(const float* __restrict__ postW,
                       const float* __restrict__ postB)
{
    __shared__ float sA[32][65];
    __shared__ float sB[32][68];
    __shared__ float sAmp[64], sAtt[64];

    int t  = threadIdx.x;
    int n0 = blockIdx.x * 64;
    if (t < 64) {
        int n = n0 + t;
        sAmp[t] = (n < N_) ? g_amp[n] : 0.f;
        sAtt[t] = (n < N_) ? g_att[n] : 0.f;
    }
    __syncthreads();

    int tx = t & 15, ty = t >> 4;
    ull acc[4][2];
#pragma unroll
    for (int i = 0; i < 4; i++) { acc[i][0] = pk2(0.f, 0.f); acc[i][1] = pk2(0.f, 0.f); }

    for (int kt = 0; kt < 26; kt++) {
#pragma unroll
        for (int r = 0; r < 2; r++) {
            int li = t + 256 * r;           /* float4 index 0..511 */
            int kl = li >> 4, c4 = li & 15;
            float4 wv = *(const float4*)(postW + (kt * 32 + kl) * 64 + c4 * 4);
            *(float4*)&sB[kl][c4 * 4] = wv;
        }
#pragma unroll
        for (int r = 0; r < 8; r++) {
            int li = t + 256 * r;
            int nl = li >> 5, kl = li & 31;
            int n  = n0 + nl;
            float v = 0.f;
            if (n < N_) {
                if (kt < 8)       v = g_agg[n * 256 + kt * 32 + kl];
                else if (kt < 16) v = g_agg[n * 256 + (kt - 8)  * 32 + kl] * sAmp[nl];
                else if (kt < 24) v = g_agg[n * 256 + (kt - 16) * 32 + kl] * sAtt[nl];
                else              v = g_x[n * 64 + (kt - 24) * 32 + kl];
            }
            sA[kl][nl] = v;
        }
        __syncthreads();
#pragma unroll 8
        for (int kk = 0; kk < 32; kk++) {
            float4 b = *(const float4*)&sB[kk][tx * 4];
            ull B01 = pk2(b.x, b.y);
            ull B23 = pk2(b.z, b.w);
#pragma unroll
            for (int i = 0; i < 4; i++) {
                float a = sA[kk][ty * 4 + i];
                ull A = pk2(a, a);
                fma2(acc[i][0], A, B01);
                fma2(acc[i][1], A, B23);
            }
        }
        __syncthreads();
    }

#pragma unroll
    for (int i = 0; i < 4; i++) {
        int n = n0 + ty * 4 + i;
        if (n >= N_) continue;
        float x0, x1, x2, x3;
        upk2(acc[i][0], x0, x1);
        upk2(acc[i][1], x2, x3);
        int c = tx * 4;
        g_y[n * 64 + c + 0] = x0 + postB[c + 0];
        g_y[n * 64 + c + 1] = x1 + postB[c + 1];
        g_y[n * 64 + c + 2] = x2 + postB[c + 2];
        g_y[n * 64 + c + 3] = x3 + postB[c + 3];
    }
}

/* ------------------------------------------------------------------ */
/* Mix + leaky_relu + snorm + residual (exact R2 version)              */
/* ------------------------------------------------------------------ */
__global__ void k_mix(const float* __restrict__ mixW,
                      const float* __restrict__ mixB,
                      const float* __restrict__ snorm)
{
    __shared__ float sY[64][65];
    __shared__ float sW[64][68];

    int t  = threadIdx.x;
    int n0 = blockIdx.x * 64;

#pragma unroll
    for (int r = 0; r < 16; r++) {
        int li = t + 256 * r;
        int nl = li >> 6, kl = li & 63;
        int n  = n0 + nl;
        sY[kl][nl] = (n < N_) ? g_y[n * 64 + kl] : 0.f;
        sW[nl][kl] = mixW[nl * 64 + kl];
    }
    __syncthreads();

    int tx = t & 15, ty = t >> 4;
    ull acc[4][2];
#pragma unroll
    for (int i = 0; i < 4; i++) { acc[i][0] = pk2(0.f, 0.f); acc[i][1] = pk2(0.f, 0.f); }

#pragma unroll 8
    for (int kk = 0; kk < 64; kk++) {
        float4 b = *(const float4*)&sW[kk][tx * 4];
        ull B01 = pk2(b.x, b.y);
        ull B23 = pk2(b.z, b.w);
#pragma unroll
        for (int i = 0; i < 4; i++) {
            float a = sY[kk][ty * 4 + i];
            ull A = pk2(a, a);
            fma2(acc[i][0], A, B01);
            fma2(acc[i][1], A, B23);
        }
    }

#pragma unroll
    for (int i = 0; i < 4; i++) {
        int n = n0 + ty * 4 + i;
        if (n >= N_) continue;
        float sn = snorm[n];
        float v[4];
        upk2(acc[i][0], v[0], v[1]);
        upk2(acc[i][1], v[2], v[3]);
#pragma unroll
        for (int j = 0; j < 4; j++) {
            int c = tx * 4 + j;
            float u = v[j] + mixB[c];
            u = (u > 0.f) ? u : 0.01f * u;
            g_x[n * 64 + c] += u * sn;
        }
    }
}

/* ------------------------------------------------------------------ */
/* Readout                                                             */
/* ------------------------------------------------------------------ */
__global__ void k_gaccum(const int* __restrict__ gid)
{
    int id = blockIdx.x * blockDim.x + threadIdx.x;
    if (id >= N_ * H_) return;
    int n = id >> 6, c = id & 63;
    atomicAdd(&g_gsum[gid[n] * 64 + c], g_x[id]);
}

__global__ void k_final(const float* __restrict__ r1W, const float* __restrict__ r1B,
                        const float* __restrict__ r2W, const float* __restrict__ r2B,
                        const float* __restrict__ r3W, const float* __restrict__ r3B,
                        float* __restrict__ out)
{
    int g = threadIdx.x;
    if (g >= G_) return;
    float cnt = fmaxf(g_gcnt[g], 1.0f);
    float hg[64];
#pragma unroll
    for (int k = 0; k < 64; k++) hg[k] = g_gsum[g * 64 + k] / cnt;

    float t1[32];
#pragma unroll
    for (int j = 0; j < 32; j++) {
        float a = r1B[j];
        for (int k = 0; k < 64; k++) a = fmaf(hg[k], r1W[k * 32 + j], a);
        t1[j] = fmaxf(a, 0.f);
    }
    float t2[16];
#pragma unroll
    for (int j = 0; j < 16; j++) {
        float a = r2B[j];
        for (int k = 0; k < 32; k++) a = fmaf(t1[k], r2W[k * 16 + j], a);
        t2[j] = fmaxf(a, 0.f);
    }
#pragma unroll
    for (int c = 0; c < 10; c++) {
        float a = r3B[c];
        for (int k = 0; k < 16; k++) a = fmaf(t2[k], r3W[k * 10 + c], a);
        out[g * 10 + c] = a;
    }
}

/* ------------------------------------------------------------------ */
/* Host launch                                                         */
/* ------------------------------------------------------------------ */
extern "C" void kernel_launch(void* const* d_in, const int* in_sizes, int n_in,
                              void* d_out, int out_size)
{
    const float* h      = (const float*)d_in[0];
    const float* snorm  = (const float*)d_in[1];
    const float* embW   = (const float*)d_in[2];
    const float* embB   = (const float*)d_in[3];
    const float* preW   = (const float*)d_in[4];
    const float* preB   = (const float*)d_in[5];
    const float* postW  = (const float*)d_in[6];
    const float* postB  = (const float*)d_in[7];
    const float* mixW   = (const float*)d_in[8];
    const float* mixB   = (const float*)d_in[9];
    const float* r1W    = (const float*)d_in[10];
    const float* r1B    = (const float*)d_in[11];
    const float* r2W    = (const float*)d_in[12];
    const float* r2B    = (const float*)d_in[13];
    const float* r3W    = (const float*)d_in[14];
    const float* r3B    = (const float*)d_in[15];
    const int*   src    = (const int*)d_in[16];
    const int*   dst    = (const int*)d_in[17];
    const int*   gid    = (const int*)d_in[18];
    float* out = (float*)d_out;

    /* launches 1-5 (setup), so layer-0 k_edge is launch #6 = ncu target */
    k_zero         <<<(N_ + 255) / 256, 256>>>();
    k_count_gcnt   <<<(E_ + 255) / 256, 256>>>(dst, gid);
    k_scan         <<<1, 1024>>>();
    k_scalers_embed<<<(N_ * H_ + 255) / 256, 256>>>(h, embW, embB);
    k_scatter      <<<(E_ + 255) / 256, 256>>>(src, dst);

    for (int i = 0; i < L_; i++) {
        k_edge<<<(E_ + 63) / 64, 256>>>(preW + i * 128 * 64, preB + i * 64);
        k_agg <<<(N_ * 32 + 255) / 256, 256>>>();
        k_post<<<(N_ + 63) / 64, 256>>>(postW + i * 832 * 64, postB + i * 64);
        k_mix <<<(N_ + 63) / 64, 256>>>(mixW + i * 64 * 64, mixB + i * 64, snorm);
    }

    k_gaccum<<<(N_ * H_ + 255) / 256, 256>>>(gid);
    k_final <<<1, 128>>>(r1W, r1B, r2W, r2B, r3W, r3B, out);
}